// round 1
// baseline (speedup 1.0000x reference)
#include <cuda_runtime.h>
#include <cstdint>
#include <cstddef>

#define N_SRC   100000
#define N_OUT   100000
#define N_EDGES 1600000
#define C       128

// ---------------- scratch (device globals; no allocation allowed) ------------
__device__ float g_Wx[(size_t)N_SRC * C];    // node-major: Wx[n][o], 51.2 MB
__device__ float g_num[(size_t)N_OUT * C];   // node-major accumulators, 51.2 MB
__device__ float g_expa[N_SRC];
__device__ float g_den[N_OUT];

// ---------------- kernel 1: zero the accumulators ----------------------------
__global__ void zero_kernel()
{
    size_t i      = (size_t)blockIdx.x * blockDim.x + threadIdx.x;
    size_t stride = (size_t)gridDim.x * blockDim.x;
    float4* np = reinterpret_cast<float4*>(g_num);
    const size_t n4 = (size_t)N_OUT * C / 4;
    for (size_t k = i; k < n4; k += stride)
        np[k] = make_float4(0.f, 0.f, 0.f, 0.f);
    for (size_t k = i; k < N_OUT; k += stride)
        g_den[k] = 0.f;
}

// ---------------- kernel 2: Wx = W @ x + b, fused score epilogue -------------
// Block tile: 128 nodes x 128 outs, BK=16, 256 threads, 8x8 micro-tile each.
// Epilogue: writes Wx[n][o] (node-major) and expa[n] = exp(leakyrelu(Wx[n].att)).
__global__ __launch_bounds__(256) void gemm_kernel(
    const float* __restrict__ x,      // (C, N_SRC)
    const float* __restrict__ W,      // (C_OUT, C_IN) row-major
    const float* __restrict__ b,      // (C,)
    const float* __restrict__ att,    // (C,)
    const float* __restrict__ alphap) // scalar
{
    __shared__ float xs[16][132];   // xs[k][n]
    __shared__ float ws[16][132];   // ws[k][o]
    __shared__ float bs[128];
    __shared__ float ats[128];
    __shared__ float sdot[128];

    const int tid   = threadIdx.x;
    const int nbase = blockIdx.x * 128;

    if (tid < 128) {
        bs[tid]   = b[tid];
        ats[tid]  = att[tid];
        sdot[tid] = 0.f;
    }

    const int tn = tid >> 4;        // 0..15 node group
    const int to = tid & 15;        // 0..15 out group

    // load mappings
    const int lc = tid >> 4;          // xs row (k) 0..15
    const int ln = (tid & 15) * 8;    // xs col (n)
    const int wo = tid >> 1;          // ws out row 0..127
    const int wc = (tid & 1) * 8;     // ws k offset

    float acc[8][8];
#pragma unroll
    for (int i = 0; i < 8; i++)
#pragma unroll
        for (int j = 0; j < 8; j++) acc[i][j] = 0.f;

    for (int c0 = 0; c0 < C; c0 += 16) {
        // global loads for this chunk
        float4 v0 = make_float4(0.f,0.f,0.f,0.f);
        float4 v1 = make_float4(0.f,0.f,0.f,0.f);
        if (nbase + ln < N_SRC) {
            const float4* xp =
                reinterpret_cast<const float4*>(&x[(size_t)(c0 + lc) * N_SRC + nbase + ln]);
            v0 = xp[0]; v1 = xp[1];
        }
        const float4* wp = reinterpret_cast<const float4*>(&W[(size_t)wo * C + c0 + wc]);
        const float4 w0 = wp[0], w1 = wp[1];

        __syncthreads();   // previous iteration finished reading smem
        *reinterpret_cast<float4*>(&xs[lc][ln])     = v0;
        *reinterpret_cast<float4*>(&xs[lc][ln + 4]) = v1;
        ws[wc + 0][wo] = w0.x; ws[wc + 1][wo] = w0.y;
        ws[wc + 2][wo] = w0.z; ws[wc + 3][wo] = w0.w;
        ws[wc + 4][wo] = w1.x; ws[wc + 5][wo] = w1.y;
        ws[wc + 6][wo] = w1.z; ws[wc + 7][wo] = w1.w;
        __syncthreads();

#pragma unroll
        for (int kk = 0; kk < 16; kk++) {
            float an[8], ao[8];
            *reinterpret_cast<float4*>(&an[0]) = *reinterpret_cast<const float4*>(&xs[kk][tn * 8]);
            *reinterpret_cast<float4*>(&an[4]) = *reinterpret_cast<const float4*>(&xs[kk][tn * 8 + 4]);
            *reinterpret_cast<float4*>(&ao[0]) = *reinterpret_cast<const float4*>(&ws[kk][to * 8]);
            *reinterpret_cast<float4*>(&ao[4]) = *reinterpret_cast<const float4*>(&ws[kk][to * 8 + 4]);
#pragma unroll
            for (int i = 0; i < 8; i++)
#pragma unroll
                for (int j = 0; j < 8; j++)
                    acc[i][j] = fmaf(an[i], ao[j], acc[i][j]);
        }
    }

    // ---- epilogue: bias, partial attention dot, Wx store ----
    float part[8];
#pragma unroll
    for (int i = 0; i < 8; i++) part[i] = 0.f;

#pragma unroll
    for (int j = 0; j < 8; j++) {
        const float bj = bs[to * 8 + j];
        const float aj = ats[to * 8 + j];
#pragma unroll
        for (int i = 0; i < 8; i++) {
            const float v = acc[i][j] + bj;
            acc[i][j] = v;
            part[i] = fmaf(v, aj, part[i]);
        }
    }

#pragma unroll
    for (int i = 0; i < 8; i++) {
        const int n = nbase + tn * 8 + i;
        if (n < N_SRC) {
            float* dst = &g_Wx[(size_t)n * C + to * 8];
            *reinterpret_cast<float4*>(dst) =
                make_float4(acc[i][0], acc[i][1], acc[i][2], acc[i][3]);
            *reinterpret_cast<float4*>(dst + 4) =
                make_float4(acc[i][4], acc[i][5], acc[i][6], acc[i][7]);
        }
    }

    // reduce attention dot across the 16 out-groups
#pragma unroll
    for (int i = 0; i < 8; i++)
        atomicAdd(&sdot[tn * 8 + i], part[i]);
    __syncthreads();

    if (tid < 128) {
        const int n = nbase + tid;
        if (n < N_SRC) {
            float a = sdot[tid];
            const float alpha = *alphap;
            a = (a >= 0.f) ? a : alpha * a;
            g_expa[n] = __expf(a);
        }
    }
}

// ---------------- kernel 3: edge scatter (1 warp per edge) -------------------
__global__ __launch_bounds__(256) void scatter_kernel(const int* __restrict__ edges)
{
    const int e    = blockIdx.x * 8 + (threadIdx.x >> 5);
    const int lane = threadIdx.x & 31;

    const int2 ts = reinterpret_cast<const int2*>(edges)[e];
    const int tgt = ts.x;
    const int src = ts.y;

    const float ex = __ldg((const float*)&g_expa[src]);

    float4 v = *reinterpret_cast<const float4*>(&g_Wx[(size_t)src * C + lane * 4]);
    v.x *= ex; v.y *= ex; v.z *= ex; v.w *= ex;

    float* np = &g_num[(size_t)tgt * C + lane * 4];
    asm volatile("red.global.add.v4.f32 [%0], {%1, %2, %3, %4};"
                 :: "l"(np), "f"(v.x), "f"(v.y), "f"(v.z), "f"(v.w)
                 : "memory");

    if (lane == 0)
        atomicAdd(&g_den[tgt], ex);
}

// ---------------- kernel 4: normalize + transpose to (C, N_OUT) --------------
__global__ __launch_bounds__(256) void finalize_kernel(float* __restrict__ out)
{
    __shared__ float tile[32][33];
    __shared__ float dsh[32];

    const int tx = threadIdx.x;       // 0..31
    const int ty = threadIdx.y;       // 0..7
    const int n0 = blockIdx.x * 32;
    const int o0 = blockIdx.y * 32;

    if (ty == 0) {
        const int n = n0 + tx;
        float d = (n < N_OUT) ? g_den[n] : 1.f;
        dsh[tx] = (d == 0.f) ? 1.f : d;
    }

#pragma unroll
    for (int r = 0; r < 4; r++) {
        const int n = n0 + ty + r * 8;
        if (n < N_OUT)
            tile[ty + r * 8][tx] = g_num[(size_t)n * C + o0 + tx];
    }
    __syncthreads();

    const float rd = 1.f / dsh[tx];
#pragma unroll
    for (int r = 0; r < 4; r++) {
        const int o = o0 + ty + r * 8;
        const int n = n0 + tx;
        if (n < N_OUT)
            out[(size_t)o * N_OUT + n] = tile[tx][ty + r * 8] * rd;
    }
}

// ---------------- launch ------------------------------------------------------
extern "C" void kernel_launch(void* const* d_in, const int* in_sizes, int n_in,
                              void* d_out, int out_size)
{
    const float* x     = (const float*)d_in[0];
    const int*   edges = (const int*)  d_in[1];
    const float* W     = (const float*)d_in[2];
    const float* b     = (const float*)d_in[3];
    const float* att   = (const float*)d_in[4];
    const float* alpha = (const float*)d_in[5];
    float* out = (float*)d_out;

    zero_kernel<<<2048, 256>>>();
    gemm_kernel<<<(N_SRC + 127) / 128, 256>>>(x, W, b, att, alpha);
    scatter_kernel<<<N_EDGES / 8, 256>>>(edges);
    dim3 fgrid((N_OUT + 31) / 32, C / 32);
    finalize_kernel<<<fgrid, dim3(32, 8)>>>(out);
}